// round 2
// baseline (speedup 1.0000x reference)
#include <cuda_runtime.h>
#include <math.h>

#define NPTS 8192
#define DDIM 64
#define NN ((size_t)NPTS * (size_t)NPTS)
#define SREG 0.1f
#define NITER 50
#define K1 33554432LL   /* 1-based rank of lower middle element (n*n/2) */

// ---- scratch (no cudaMalloc allowed) ----
__device__ float g_M[67108864];   // 256 MB cost matrix (unnormalized)
__device__ float g_K[67108864];   // 256 MB Gibbs kernel
__device__ float g_u[NPTS], g_v[NPTS], g_tmp[NPTS];
__device__ float g_x2[NPTS], g_y2[NPTS];
__device__ unsigned int g_hist[2048];
__device__ unsigned int g_prefix;
__device__ long long g_k;
__device__ unsigned long long g_cntLE;
__device__ unsigned int g_minGT;
__device__ float g_invMedReg;
__device__ float g_lossScale;
__device__ double g_loss;

// ---------------- init ----------------
__global__ void k_init() {
    int idx = blockIdx.x * blockDim.x + threadIdx.x;
    if (idx < NPTS) { g_u[idx] = 1.0f / NPTS; g_tmp[idx] = 0.0f; }
    if (idx < 2048) g_hist[idx] = 0;
    if (idx == 0) {
        g_loss = 0.0;
        g_prefix = 0u;
        g_k = K1;
        g_cntLE = 0ULL;
        g_minGT = 0xFFFFFFFFu;
    }
}

// ---------------- row norms (warp per row) ----------------
__global__ void k_norms(const float* __restrict__ X, const float* __restrict__ Y) {
    int gw = (blockIdx.x * blockDim.x + threadIdx.x) >> 5;
    int lane = threadIdx.x & 31;
    if (gw >= 2 * NPTS) return;
    const float* src = (gw < NPTS) ? X : Y;
    int row = (gw < NPTS) ? gw : gw - NPTS;
    float2 p = ((const float2*)(src + (size_t)row * DDIM))[lane];
    float s = p.x * p.x + p.y * p.y;
    #pragma unroll
    for (int o = 16; o; o >>= 1) s += __shfl_xor_sync(0xFFFFFFFFu, s, o);
    if (lane == 0) { if (gw < NPTS) g_x2[row] = s; else g_y2[row] = s; }
}

// ---------------- M = sq-cdist GEMM + fused level-0 histogram ----------------
__global__ void k_gemm(const float* __restrict__ X, const float* __restrict__ Y) {
    __shared__ float Xs[64][65];
    __shared__ float Ys[64][65];
    __shared__ unsigned int sh[2048];
    int tx = threadIdx.x, ty = threadIdx.y;
    int tid = ty * 16 + tx;
    int i0 = blockIdx.y * 64, j0 = blockIdx.x * 64;

    for (int t = tid; t < 2048; t += 256) sh[t] = 0u;
    for (int t = tid; t < 4096; t += 256) {
        int r = t >> 6, c = t & 63;
        Xs[r][c] = X[(size_t)(i0 + r) * DDIM + c];
        Ys[r][c] = Y[(size_t)(j0 + r) * DDIM + c];
    }
    __syncthreads();

    float acc[4][4] = {};
    #pragma unroll 16
    for (int k = 0; k < 64; k++) {
        float a[4], b[4];
        #pragma unroll
        for (int r = 0; r < 4; r++) a[r] = Xs[ty * 4 + r][k];
        #pragma unroll
        for (int c = 0; c < 4; c++) b[c] = Ys[tx * 4 + c][k];
        #pragma unroll
        for (int r = 0; r < 4; r++)
            #pragma unroll
            for (int c = 0; c < 4; c++) acc[r][c] += a[r] * b[c];
    }

    #pragma unroll
    for (int r = 0; r < 4; r++) {
        int i = i0 + ty * 4 + r;
        float xi = g_x2[i];
        float4 outv;
        float* o = &outv.x;
        #pragma unroll
        for (int c = 0; c < 4; c++) {
            int j = j0 + tx * 4 + c;
            float m = fmaxf(xi + g_y2[j] - 2.0f * acc[r][c], 0.0f);
            o[c] = m;
            atomicAdd(&sh[__float_as_uint(m) >> 21], 1u);
        }
        *(float4*)&g_M[(size_t)i * NPTS + j0 + tx * 4] = outv;
    }
    __syncthreads();
    for (int t = tid; t < 2048; t += 256)
        if (sh[t]) atomicAdd(&g_hist[t], sh[t]);
}

// ---------------- radix-select scan (1 thread) ----------------
__global__ void k_scan(int level) {
    int bits = (level < 2) ? 11 : 10;
    int bins = 1 << bits;
    long long k = g_k, c = 0;
    int b = 0;
    for (; b < bins - 1; b++) {
        long long h = (long long)g_hist[b];
        if (c + h >= k) break;
        c += h;
    }
    g_k = k - c;
    g_prefix = (g_prefix << bits) | (unsigned)b;
    for (int t = 0; t < 2048; t++) g_hist[t] = 0u;
}

// ---------------- filtered histogram passes (levels 1, 2) ----------------
__global__ void k_hist(int level) {
    __shared__ unsigned int sh[2048];
    int tid = threadIdx.x;
    for (int t = tid; t < 2048; t += blockDim.x) sh[t] = 0u;
    __syncthreads();
    unsigned pref = g_prefix;
    size_t stride = (size_t)gridDim.x * blockDim.x;
    for (size_t idx = (size_t)blockIdx.x * blockDim.x + tid; idx < NN; idx += stride) {
        unsigned bv = __float_as_uint(g_M[idx]);
        if (level == 1) {
            if ((bv >> 21) == pref) atomicAdd(&sh[(bv >> 10) & 2047u], 1u);
        } else {
            if ((bv >> 10) == pref) atomicAdd(&sh[bv & 1023u], 1u);
        }
    }
    __syncthreads();
    for (int t = tid; t < 2048; t += blockDim.x)
        if (sh[t]) atomicAdd(&g_hist[t], sh[t]);
}

// ---------------- count <= v1, min of elements > v1 ----------------
__global__ void k_cntmin() {
    unsigned v1 = g_prefix;
    unsigned long long cnt = 0ULL;
    unsigned mn = 0xFFFFFFFFu;
    size_t stride = (size_t)gridDim.x * blockDim.x;
    for (size_t idx = (size_t)blockIdx.x * blockDim.x + threadIdx.x; idx < NN; idx += stride) {
        unsigned bv = __float_as_uint(g_M[idx]);
        if (bv <= v1) cnt++;
        else mn = min(mn, bv);
    }
    #pragma unroll
    for (int o = 16; o; o >>= 1) {
        cnt += __shfl_xor_sync(0xFFFFFFFFu, cnt, o);
        mn = min(mn, __shfl_xor_sync(0xFFFFFFFFu, mn, o));
    }
    if ((threadIdx.x & 31) == 0) {
        atomicAdd(&g_cntLE, cnt);
        atomicMin(&g_minGT, mn);
    }
}

// ---------------- median finalize ----------------
__global__ void k_med() {
    float v1 = __uint_as_float(g_prefix);
    float v2 = (g_cntLE >= (unsigned long long)(K1 + 1)) ? v1 : __uint_as_float(g_minGT);
    float med = 0.5f * (v1 + v2);
    if (med > 0.0f) {
        g_invMedReg = 1.0f / (med * SREG);
        g_lossScale = 1.0f / med;
    } else {
        g_invMedReg = 1.0f / SREG;
        g_lossScale = 1.0f;
    }
}

// ---------------- K = exp(-M * invMedReg) ----------------
__global__ void k_gibbs() {
    float inv = g_invMedReg;
    size_t stride = (size_t)gridDim.x * blockDim.x;
    const float4* Mi = (const float4*)g_M;
    float4* Ko = (float4*)g_K;
    for (size_t q = (size_t)blockIdx.x * blockDim.x + threadIdx.x; q < NN / 4; q += stride) {
        float4 m = Mi[q];
        float4 kk;
        kk.x = expf(-m.x * inv);
        kk.y = expf(-m.y * inv);
        kk.z = expf(-m.z * inv);
        kk.w = expf(-m.w * inv);
        Ko[q] = kk;
    }
}

// ---------------- tmp_j += sum_i K_ij * u_i  (K^T u, column-tiled) ----------------
__global__ void k_colsum() {
    int j = (blockIdx.x * 256 + threadIdx.x) * 4;
    int r0 = blockIdx.y * 256;
    float4 acc = make_float4(0.f, 0.f, 0.f, 0.f);
    #pragma unroll 4
    for (int r = 0; r < 256; r++) {
        float uu = g_u[r0 + r];
        float4 kv = *(const float4*)(g_K + (size_t)(r0 + r) * NPTS + j);
        acc.x += kv.x * uu; acc.y += kv.y * uu;
        acc.z += kv.z * uu; acc.w += kv.w * uu;
    }
    atomicAdd(&g_tmp[j + 0], acc.x);
    atomicAdd(&g_tmp[j + 1], acc.y);
    atomicAdd(&g_tmp[j + 2], acc.z);
    atomicAdd(&g_tmp[j + 3], acc.w);
}

// ---------------- v = nu / tmp ; tmp = 0 ----------------
__global__ void k_vupd() {
    int j = blockIdx.x * blockDim.x + threadIdx.x;
    if (j < NPTS) {
        g_v[j] = (1.0f / NPTS) / g_tmp[j];
        g_tmp[j] = 0.0f;
    }
}

// ---------------- u_i = mu / sum_j K_ij v_j  (warp per row) ----------------
__global__ void k_rowdot() {
    int warp = threadIdx.x >> 5, lane = threadIdx.x & 31;
    int row = blockIdx.x * 8 + warp;
    const float4* Kr = (const float4*)(g_K + (size_t)row * NPTS);
    const float4* V = (const float4*)g_v;
    float4 acc = make_float4(0.f, 0.f, 0.f, 0.f);
    #pragma unroll 8
    for (int c = lane; c < NPTS / 4; c += 32) {
        float4 kv = Kr[c];
        float4 vv = V[c];
        acc.x += kv.x * vv.x; acc.y += kv.y * vv.y;
        acc.z += kv.z * vv.z; acc.w += kv.w * vv.w;
    }
    float s = (acc.x + acc.y) + (acc.z + acc.w);
    #pragma unroll
    for (int o = 16; o; o >>= 1) s += __shfl_xor_sync(0xFFFFFFFFu, s, o);
    if (lane == 0) g_u[row] = (1.0f / NPTS) / s;
}

// ---------------- loss = sum u_i K_ij v_j M_ij ----------------
__global__ void k_loss() {
    double acc = 0.0;
    size_t stride = (size_t)gridDim.x * blockDim.x;
    const float4* Kp = (const float4*)g_K;
    const float4* Mp = (const float4*)g_M;
    const float4* Vp = (const float4*)g_v;
    for (size_t q = (size_t)blockIdx.x * blockDim.x + threadIdx.x; q < NN / 4; q += stride) {
        size_t i = q >> 11;        // q*4 / 8192
        int j4 = (int)(q & 2047);
        float4 k4 = Kp[q];
        float4 m4 = Mp[q];
        float4 v4 = Vp[j4];
        float ui = g_u[i];
        float t = k4.x * v4.x * m4.x + k4.y * v4.y * m4.y
                + k4.z * v4.z * m4.z + k4.w * v4.w * m4.w;
        acc += (double)ui * (double)t;
    }
    #pragma unroll
    for (int o = 16; o; o >>= 1) acc += __shfl_xor_sync(0xFFFFFFFFu, acc, o);
    __shared__ double sh[8];
    int warp = threadIdx.x >> 5, lane = threadIdx.x & 31;
    if (lane == 0) sh[warp] = acc;
    __syncthreads();
    if (threadIdx.x == 0) {
        double s = 0.0;
        #pragma unroll
        for (int w = 0; w < 8; w++) s += sh[w];
        atomicAdd(&g_loss, s);
    }
}

__global__ void k_out(float* out) {
    out[0] = (float)(g_loss * (double)g_lossScale);
}

extern "C" void kernel_launch(void* const* d_in, const int* in_sizes, int n_in,
                              void* d_out, int out_size) {
    const float* X = (const float*)d_in[0];
    const float* Y = (const float*)d_in[1];

    k_init<<<32, 256>>>();
    k_norms<<<2048, 256>>>(X, Y);
    k_gemm<<<dim3(128, 128), dim3(16, 16)>>>(X, Y);
    k_scan<<<1, 1>>>(0);
    k_hist<<<2048, 256>>>(1);
    k_scan<<<1, 1>>>(1);
    k_hist<<<2048, 256>>>(2);
    k_scan<<<1, 1>>>(2);
    k_cntmin<<<2048, 256>>>();
    k_med<<<1, 1>>>();
    k_gibbs<<<4096, 256>>>();

    for (int it = 0; it < NITER; it++) {
        k_colsum<<<dim3(8, 32), 256>>>();
        k_vupd<<<32, 256>>>();
        k_rowdot<<<1024, 256>>>();
    }

    k_loss<<<1024, 256>>>();
    k_out<<<1, 1>>>((float*)d_out);
}

// round 4
// speedup vs baseline: 1.0383x; 1.0383x over previous
#include <cuda_runtime.h>
#include <cuda_fp16.h>
#include <math.h>

#define NPTS 8192
#define DDIM 64
#define NN ((size_t)NPTS * (size_t)NPTS)
#define NITER 50
#define K1 33554432LL   /* 1-based rank of lower middle element (n*n/2) */

// ---- scratch (no cudaMalloc allowed) ----
__device__ float  g_M[67108864];    // 256 MB cost matrix (unnormalized)
__device__ __half g_Kh[67108864];   // 128 MB scaled Gibbs kernel  K' = e^10 * K
__device__ float g_u[NPTS], g_v[NPTS], g_tmp[NPTS];
__device__ float g_x2[NPTS], g_y2[NPTS];
__device__ unsigned int g_hist0[2048], g_hist1[2048], g_hist2[1024];
__device__ unsigned int g_prefix;
__device__ long long g_k;
__device__ unsigned long long g_cntLE;
__device__ unsigned int g_minGT;
__device__ float g_invMedReg;   // 1/(med*0.1)
__device__ float g_lossScale;   // 1/med
__device__ double g_loss;

// ---------------- init ----------------
__global__ void k_init() {
    int idx = blockIdx.x * blockDim.x + threadIdx.x;
    if (idx < NPTS) { g_u[idx] = 1.0f / NPTS; g_tmp[idx] = 0.0f; }
    if (idx < 2048) { g_hist0[idx] = 0u; g_hist1[idx] = 0u; }
    if (idx < 1024) g_hist2[idx] = 0u;
    if (idx == 0) {
        g_loss = 0.0;
        g_prefix = 0u;
        g_k = K1;
        g_cntLE = 0ULL;
        g_minGT = 0xFFFFFFFFu;
    }
}

// ---------------- row norms (warp per row) ----------------
__global__ void k_norms(const float* __restrict__ X, const float* __restrict__ Y) {
    int gw = (blockIdx.x * blockDim.x + threadIdx.x) >> 5;
    int lane = threadIdx.x & 31;
    if (gw >= 2 * NPTS) return;
    const float* src = (gw < NPTS) ? X : Y;
    int row = (gw < NPTS) ? gw : gw - NPTS;
    float2 p = ((const float2*)(src + (size_t)row * DDIM))[lane];
    float s = p.x * p.x + p.y * p.y;
    #pragma unroll
    for (int o = 16; o; o >>= 1) s += __shfl_xor_sync(0xFFFFFFFFu, s, o);
    if (lane == 0) { if (gw < NPTS) g_x2[row] = s; else g_y2[row] = s; }
}

// ---------------- M = sq-cdist GEMM + fused level-0 histogram ----------------
__global__ void k_gemm(const float* __restrict__ X, const float* __restrict__ Y) {
    __shared__ float Xs[64][65];
    __shared__ float Ys[64][65];
    __shared__ unsigned int sh[2048];
    int tx = threadIdx.x, ty = threadIdx.y;
    int tid = ty * 16 + tx;
    int lane = tid & 31;
    int i0 = blockIdx.y * 64, j0 = blockIdx.x * 64;

    for (int t = tid; t < 2048; t += 256) sh[t] = 0u;
    for (int t = tid; t < 4096; t += 256) {
        int r = t >> 6, c = t & 63;
        Xs[r][c] = X[(size_t)(i0 + r) * DDIM + c];
        Ys[r][c] = Y[(size_t)(j0 + r) * DDIM + c];
    }
    __syncthreads();

    float acc[4][4] = {};
    #pragma unroll 16
    for (int k = 0; k < 64; k++) {
        float a[4], b[4];
        #pragma unroll
        for (int r = 0; r < 4; r++) a[r] = Xs[ty * 4 + r][k];
        #pragma unroll
        for (int c = 0; c < 4; c++) b[c] = Ys[tx * 4 + c][k];
        #pragma unroll
        for (int r = 0; r < 4; r++)
            #pragma unroll
            for (int c = 0; c < 4; c++) acc[r][c] += a[r] * b[c];
    }

    #pragma unroll
    for (int r = 0; r < 4; r++) {
        int i = i0 + ty * 4 + r;
        float xi = g_x2[i];
        float4 outv;
        float* o = &outv.x;
        #pragma unroll
        for (int c = 0; c < 4; c++) {
            int j = j0 + tx * 4 + c;
            float m = fmaxf(xi + g_y2[j] - 2.0f * acc[r][c], 0.0f);
            o[c] = m;
            unsigned bin = __float_as_uint(m) >> 21;
            unsigned mask = __match_any_sync(0xFFFFFFFFu, bin);
            if (lane == (__ffs(mask) - 1)) atomicAdd(&sh[bin], (unsigned)__popc(mask));
        }
        *(float4*)&g_M[(size_t)i * NPTS + j0 + tx * 4] = outv;
    }
    __syncthreads();
    for (int t = tid; t < 2048; t += 256)
        if (sh[t]) atomicAdd(&g_hist0[t], sh[t]);
}

// ---------------- radix-select scan (block-cooperative, compile-time level) ----------------
template <int LEVEL>
__global__ void k_scan() {
    constexpr int BITS = (LEVEL < 2) ? 11 : 10;
    constexpr int PER = (1 << BITS) >> 8;   // 8 or 4
    __shared__ unsigned int sums[256];
    __shared__ int sh_b;
    __shared__ long long sh_k;
    int t = threadIdx.x;
    const unsigned int* hist = (LEVEL == 0) ? g_hist0 : (LEVEL == 1) ? g_hist1 : g_hist2;
    unsigned int vals[PER];
    unsigned int local = 0;
    #pragma unroll
    for (int i = 0; i < PER; i++) { vals[i] = hist[t * PER + i]; local += vals[i]; }
    sums[t] = local;
    __syncthreads();
    if (t == 0) {
        long long k = g_k, c = 0;
        int b = 0;
        for (; b < 255; b++) {
            long long h = (long long)sums[b];
            if (c + h >= k) break;
            c += h;
        }
        sh_b = b;
        sh_k = k - c;
    }
    __syncthreads();
    if (t == sh_b) {
        long long k2 = sh_k, c = 0;
        int sel = PER - 1;
        #pragma unroll
        for (int i = 0; i < PER - 1; i++) {
            long long h = (long long)vals[i];
            if (sel == PER - 1) {                // still searching
                if (c + h >= k2) sel = i;
                else c += h;
            }
        }
        // note: if sel found early we stopped accumulating; c holds prefix below sel
        g_k = k2 - c;
        g_prefix = (g_prefix << BITS) | (unsigned)(t * PER + sel);
    }
}

// ---------------- filtered histogram passes (levels 1, 2) ----------------
template <int LEVEL>
__global__ void k_hist() {
    constexpr int NB = (LEVEL == 1) ? 2048 : 1024;
    __shared__ unsigned int sh[NB];
    int tid = threadIdx.x;
    for (int t = tid; t < NB; t += blockDim.x) sh[t] = 0u;
    __syncthreads();
    unsigned pref = g_prefix;
    size_t stride = (size_t)gridDim.x * blockDim.x;
    for (size_t idx = (size_t)blockIdx.x * blockDim.x + tid; idx < NN; idx += stride) {
        unsigned bv = __float_as_uint(g_M[idx]);
        if (LEVEL == 1) {
            if ((bv >> 21) == pref) atomicAdd(&sh[(bv >> 10) & 2047u], 1u);
        } else {
            if ((bv >> 10) == pref) atomicAdd(&sh[bv & 1023u], 1u);
        }
    }
    __syncthreads();
    unsigned int* dst = (LEVEL == 1) ? g_hist1 : g_hist2;
    for (int t = tid; t < NB; t += blockDim.x)
        if (sh[t]) atomicAdd(&dst[t], sh[t]);
}

// ---------------- count <= v1, min of elements > v1 ----------------
__global__ void k_cntmin() {
    unsigned v1 = g_prefix;
    unsigned long long cnt = 0ULL;
    unsigned mn = 0xFFFFFFFFu;
    size_t stride = (size_t)gridDim.x * blockDim.x;
    for (size_t idx = (size_t)blockIdx.x * blockDim.x + threadIdx.x; idx < NN; idx += stride) {
        unsigned bv = __float_as_uint(g_M[idx]);
        if (bv <= v1) cnt++;
        else mn = min(mn, bv);
    }
    #pragma unroll
    for (int o = 16; o; o >>= 1) {
        cnt += __shfl_xor_sync(0xFFFFFFFFu, cnt, o);
        mn = min(mn, __shfl_xor_sync(0xFFFFFFFFu, mn, o));
    }
    if ((threadIdx.x & 31) == 0) {
        atomicAdd(&g_cntLE, cnt);
        atomicMin(&g_minGT, mn);
    }
}

// ---------------- median finalize ----------------
__global__ void k_med() {
    float v1 = __uint_as_float(g_prefix);
    float v2 = (g_cntLE >= (unsigned long long)(K1 + 1)) ? v1 : __uint_as_float(g_minGT);
    float med = 0.5f * (v1 + v2);
    if (med > 0.0f) {
        g_invMedReg = 10.0f / med;   // SREG = 0.1
        g_lossScale = 1.0f / med;
    } else {
        g_invMedReg = 10.0f;
        g_lossScale = 1.0f;
    }
}

// ---------------- K' = e^10 * exp(-M * invMedReg)  (fp16) ----------------
// Constant rescale by e^10 keeps values in fp16 normal range; Sinkhorn u and
// the loss contraction sum u*K'*v'*M are exactly invariant under this scaling.
__global__ void k_gibbs() {
    float inv = g_invMedReg;
    size_t stride = (size_t)gridDim.x * blockDim.x;
    const float4* Mi = (const float4*)g_M;
    uint4* Ko = (uint4*)g_Kh;
    for (size_t q = (size_t)blockIdx.x * blockDim.x + threadIdx.x; q < NN / 8; q += stride) {
        float4 m0 = Mi[2 * q];
        float4 m1 = Mi[2 * q + 1];
        __half2 h0 = __floats2half2_rn(__expf(10.0f - m0.x * inv), __expf(10.0f - m0.y * inv));
        __half2 h1 = __floats2half2_rn(__expf(10.0f - m0.z * inv), __expf(10.0f - m0.w * inv));
        __half2 h2 = __floats2half2_rn(__expf(10.0f - m1.x * inv), __expf(10.0f - m1.y * inv));
        __half2 h3 = __floats2half2_rn(__expf(10.0f - m1.z * inv), __expf(10.0f - m1.w * inv));
        uint4 o;
        o.x = *(unsigned int*)&h0;
        o.y = *(unsigned int*)&h1;
        o.z = *(unsigned int*)&h2;
        o.w = *(unsigned int*)&h3;
        Ko[q] = o;
    }
}

// ---------------- tmp_j += sum_i K'_ij * u_i  (K'^T u, column-tiled) ----------------
__global__ void k_colsum() {
    __shared__ float us[256];
    int tid = threadIdx.x;
    int j8 = blockIdx.x * 256 + tid;            // uint4 column index, 0..1023
    int r0 = blockIdx.y * 256;
    us[tid] = g_u[r0 + tid];
    __syncthreads();
    const uint4* Kb = (const uint4*)(g_Kh + (size_t)r0 * NPTS) + j8;
    float a0 = 0.f, a1 = 0.f, a2 = 0.f, a3 = 0.f, a4 = 0.f, a5 = 0.f, a6 = 0.f, a7 = 0.f;
    #pragma unroll 4
    for (int r = 0; r < 256; r++) {
        float uu = us[r];
        uint4 kv = Kb[(size_t)r * (NPTS / 8)];
        float2 f0 = __half22float2(*(__half2*)&kv.x);
        float2 f1 = __half22float2(*(__half2*)&kv.y);
        float2 f2 = __half22float2(*(__half2*)&kv.z);
        float2 f3 = __half22float2(*(__half2*)&kv.w);
        a0 += f0.x * uu; a1 += f0.y * uu;
        a2 += f1.x * uu; a3 += f1.y * uu;
        a4 += f2.x * uu; a5 += f2.y * uu;
        a6 += f3.x * uu; a7 += f3.y * uu;
    }
    int j = j8 * 8;
    atomicAdd(&g_tmp[j + 0], a0); atomicAdd(&g_tmp[j + 1], a1);
    atomicAdd(&g_tmp[j + 2], a2); atomicAdd(&g_tmp[j + 3], a3);
    atomicAdd(&g_tmp[j + 4], a4); atomicAdd(&g_tmp[j + 5], a5);
    atomicAdd(&g_tmp[j + 6], a6); atomicAdd(&g_tmp[j + 7], a7);
}

// ---------------- v' = nu / tmp ; tmp = 0 ----------------
__global__ void k_vupd() {
    int j = blockIdx.x * blockDim.x + threadIdx.x;
    if (j < NPTS) {
        g_v[j] = (1.0f / NPTS) / g_tmp[j];
        g_tmp[j] = 0.0f;
    }
}

// ---------------- u_i = mu / sum_j K'_ij v'_j  (warp per row) ----------------
__global__ void k_rowdot() {
    int warp = threadIdx.x >> 5, lane = threadIdx.x & 31;
    int row = blockIdx.x * 8 + warp;
    const uint4* Kr = (const uint4*)(g_Kh + (size_t)row * NPTS);
    const float4* V = (const float4*)g_v;
    float s0 = 0.f, s1 = 0.f, s2 = 0.f, s3 = 0.f;
    #pragma unroll 8
    for (int c = lane; c < NPTS / 8; c += 32) {
        uint4 kv = Kr[c];
        float4 va = V[2 * c], vb = V[2 * c + 1];
        float2 f0 = __half22float2(*(__half2*)&kv.x);
        float2 f1 = __half22float2(*(__half2*)&kv.y);
        float2 f2 = __half22float2(*(__half2*)&kv.z);
        float2 f3 = __half22float2(*(__half2*)&kv.w);
        s0 += f0.x * va.x + f0.y * va.y;
        s1 += f1.x * va.z + f1.y * va.w;
        s2 += f2.x * vb.x + f2.y * vb.y;
        s3 += f3.x * vb.z + f3.y * vb.w;
    }
    float s = (s0 + s1) + (s2 + s3);
    #pragma unroll
    for (int o = 16; o; o >>= 1) s += __shfl_xor_sync(0xFFFFFFFFu, s, o);
    if (lane == 0) g_u[row] = (1.0f / NPTS) / s;
}

// ---------------- loss = sum u_i K'_ij v'_j M_ij ----------------
__global__ void k_loss() {
    double acc = 0.0;
    size_t stride = (size_t)gridDim.x * blockDim.x;
    const uint4* Kp = (const uint4*)g_Kh;
    const float4* Mp = (const float4*)g_M;
    const float4* Vp = (const float4*)g_v;
    for (size_t q = (size_t)blockIdx.x * blockDim.x + threadIdx.x; q < NN / 8; q += stride) {
        size_t i = q >> 10;          // q*8 / 8192
        int j8 = (int)(q & 1023);
        uint4 kq = Kp[q];
        float4 m0 = Mp[2 * q], m1 = Mp[2 * q + 1];
        float4 va = Vp[2 * j8], vb = Vp[2 * j8 + 1];
        float2 f0 = __half22float2(*(__half2*)&kq.x);
        float2 f1 = __half22float2(*(__half2*)&kq.y);
        float2 f2 = __half22float2(*(__half2*)&kq.z);
        float2 f3 = __half22float2(*(__half2*)&kq.w);
        float ui = g_u[i];
        float t = f0.x * va.x * m0.x + f0.y * va.y * m0.y
                + f1.x * va.z * m0.z + f1.y * va.w * m0.w
                + f2.x * vb.x * m1.x + f2.y * vb.y * m1.y
                + f3.x * vb.z * m1.z + f3.y * vb.w * m1.w;
        acc += (double)ui * (double)t;
    }
    #pragma unroll
    for (int o = 16; o; o >>= 1) acc += __shfl_xor_sync(0xFFFFFFFFu, acc, o);
    __shared__ double sh[8];
    int warp = threadIdx.x >> 5, lane = threadIdx.x & 31;
    if (lane == 0) sh[warp] = acc;
    __syncthreads();
    if (threadIdx.x == 0) {
        double s = 0.0;
        #pragma unroll
        for (int w = 0; w < 8; w++) s += sh[w];
        atomicAdd(&g_loss, s);
    }
}

__global__ void k_out(float* out) {
    out[0] = (float)(g_loss * (double)g_lossScale);
}

extern "C" void kernel_launch(void* const* d_in, const int* in_sizes, int n_in,
                              void* d_out, int out_size) {
    const float* X = (const float*)d_in[0];
    const float* Y = (const float*)d_in[1];

    k_init<<<32, 256>>>();
    k_norms<<<2048, 256>>>(X, Y);
    k_gemm<<<dim3(128, 128), dim3(16, 16)>>>(X, Y);
    k_scan<0><<<1, 256>>>();
    k_hist<1><<<2048, 256>>>();
    k_scan<1><<<1, 256>>>();
    k_hist<2><<<2048, 256>>>();
    k_scan<2><<<1, 256>>>();
    k_cntmin<<<2048, 256>>>();
    k_med<<<1, 1>>>();
    k_gibbs<<<2048, 256>>>();

    for (int it = 0; it < NITER; it++) {
        k_colsum<<<dim3(4, 32), 256>>>();
        k_vupd<<<32, 256>>>();
        k_rowdot<<<1024, 256>>>();
    }

    k_loss<<<1024, 256>>>();
    k_out<<<1, 1>>>((float*)d_out);
}

// round 7
// speedup vs baseline: 1.4807x; 1.4260x over previous
#include <cuda_runtime.h>
#include <cuda_fp16.h>
#include <math.h>

#define NPTS 8192
#define DDIM 64
#define NN ((size_t)NPTS * (size_t)NPTS)
#define NITER 50
#define K1 33554432LL   /* 1-based rank of lower middle element (n*n/2) */

// ---- scratch (no cudaMalloc allowed) ----
__device__ float  g_M[67108864];    // 256 MB cost matrix (unnormalized)
__device__ __half g_Kh[67108864];   // 128 MB scaled Gibbs kernel  K' = e^10 * K
__device__ float g_u[NPTS], g_v[NPTS], g_tmp[NPTS];
__device__ float g_x2[NPTS], g_y2[NPTS];
__device__ unsigned int g_hist0[2048], g_hist1[2048], g_hist2[1024];
__device__ unsigned int g_prefix;
__device__ long long g_k;
__device__ unsigned long long g_cntLE;
__device__ unsigned int g_minGT;
__device__ float g_invMedReg;       // 10/med
__device__ float g_lossScale;       // 1/med
__device__ double g_loss;

// ---------------- init ----------------
__global__ void k_init() {
    int idx = blockIdx.x * blockDim.x + threadIdx.x;
    if (idx < NPTS) { g_u[idx] = 1.0f / NPTS; g_tmp[idx] = 0.0f; }
    if (idx < 2048) { g_hist0[idx] = 0u; g_hist1[idx] = 0u; }
    if (idx < 1024) g_hist2[idx] = 0u;
    if (idx == 0) {
        g_loss = 0.0;
        g_prefix = 0u;
        g_k = K1;
        g_cntLE = 0ULL;
        g_minGT = 0xFFFFFFFFu;
    }
}

// ---------------- row norms (warp per row) ----------------
__global__ void k_norms(const float* __restrict__ X, const float* __restrict__ Y) {
    int gw = (blockIdx.x * blockDim.x + threadIdx.x) >> 5;
    int lane = threadIdx.x & 31;
    if (gw >= 2 * NPTS) return;
    const float* src = (gw < NPTS) ? X : Y;
    int row = (gw < NPTS) ? gw : gw - NPTS;
    float2 p = ((const float2*)(src + (size_t)row * DDIM))[lane];
    float s = p.x * p.x + p.y * p.y;
    #pragma unroll
    for (int o = 16; o; o >>= 1) s += __shfl_xor_sync(0xFFFFFFFFu, s, o);
    if (lane == 0) { if (gw < NPTS) g_x2[row] = s; else g_y2[row] = s; }
}

// ---------------- M = sq-cdist GEMM + fused level-0 histogram ----------------
__global__ void k_gemm(const float* __restrict__ X, const float* __restrict__ Y) {
    __shared__ float Xs[64][65];
    __shared__ float Ys[64][65];
    __shared__ unsigned int sh[2048];
    int tx = threadIdx.x, ty = threadIdx.y;
    int tid = ty * 16 + tx;
    int lane = tid & 31;
    int i0 = blockIdx.y * 64, j0 = blockIdx.x * 64;

    for (int t = tid; t < 2048; t += 256) sh[t] = 0u;
    for (int t = tid; t < 4096; t += 256) {
        int r = t >> 6, c = t & 63;
        Xs[r][c] = X[(size_t)(i0 + r) * DDIM + c];
        Ys[r][c] = Y[(size_t)(j0 + r) * DDIM + c];
    }
    __syncthreads();

    float acc[4][4] = {};
    #pragma unroll 16
    for (int k = 0; k < 64; k++) {
        float a[4], b[4];
        #pragma unroll
        for (int r = 0; r < 4; r++) a[r] = Xs[ty * 4 + r][k];
        #pragma unroll
        for (int c = 0; c < 4; c++) b[c] = Ys[tx * 4 + c][k];
        #pragma unroll
        for (int r = 0; r < 4; r++)
            #pragma unroll
            for (int c = 0; c < 4; c++) acc[r][c] += a[r] * b[c];
    }

    #pragma unroll
    for (int r = 0; r < 4; r++) {
        int i = i0 + ty * 4 + r;
        float xi = g_x2[i];
        float4 outv;
        float* o = &outv.x;
        #pragma unroll
        for (int c = 0; c < 4; c++) {
            int j = j0 + tx * 4 + c;
            float m = fmaxf(xi + g_y2[j] - 2.0f * acc[r][c], 0.0f);
            o[c] = m;
            unsigned bin = __float_as_uint(m) >> 21;
            unsigned mask = __match_any_sync(0xFFFFFFFFu, bin);
            if (lane == (__ffs(mask) - 1)) atomicAdd(&sh[bin], (unsigned)__popc(mask));
        }
        *(float4*)&g_M[(size_t)i * NPTS + j0 + tx * 4] = outv;
    }
    __syncthreads();
    for (int t = tid; t < 2048; t += 256)
        if (sh[t]) atomicAdd(&g_hist0[t], sh[t]);
}

// ---------------- radix-select scan (block-cooperative, compile-time level) ----------------
template <int LEVEL>
__global__ void k_scan() {
    constexpr int BITS = (LEVEL < 2) ? 11 : 10;
    constexpr int PER = (1 << BITS) >> 8;   // 8 or 4
    __shared__ unsigned int sums[256];
    __shared__ int sh_b;
    __shared__ long long sh_k;
    int t = threadIdx.x;
    const unsigned int* hist = (LEVEL == 0) ? g_hist0 : (LEVEL == 1) ? g_hist1 : g_hist2;
    unsigned int vals[PER];
    unsigned int local = 0;
    #pragma unroll
    for (int i = 0; i < PER; i++) { vals[i] = hist[t * PER + i]; local += vals[i]; }
    sums[t] = local;
    __syncthreads();
    if (t == 0) {
        long long k = g_k, c = 0;
        int b = 0;
        for (; b < 255; b++) {
            long long h = (long long)sums[b];
            if (c + h >= k) break;
            c += h;
        }
        sh_b = b;
        sh_k = k - c;
    }
    __syncthreads();
    if (t == sh_b) {
        long long k2 = sh_k, c = 0;
        int sel = PER - 1;
        #pragma unroll
        for (int i = 0; i < PER - 1; i++) {
            long long h = (long long)vals[i];
            if (sel == PER - 1) {
                if (c + h >= k2) sel = i;
                else c += h;
            }
        }
        g_k = k2 - c;
        g_prefix = (g_prefix << BITS) | (unsigned)(t * PER + sel);
    }
}

// ---------------- filtered histogram passes (levels 1, 2) ----------------
template <int LEVEL>
__global__ void k_hist() {
    constexpr int NB = (LEVEL == 1) ? 2048 : 1024;
    __shared__ unsigned int sh[NB];
    int tid = threadIdx.x;
    for (int t = tid; t < NB; t += blockDim.x) sh[t] = 0u;
    __syncthreads();
    unsigned pref = g_prefix;
    size_t stride = (size_t)gridDim.x * blockDim.x;
    for (size_t idx = (size_t)blockIdx.x * blockDim.x + tid; idx < NN; idx += stride) {
        unsigned bv = __float_as_uint(g_M[idx]);
        if (LEVEL == 1) {
            if ((bv >> 21) == pref) atomicAdd(&sh[(bv >> 10) & 2047u], 1u);
        } else {
            if ((bv >> 10) == pref) atomicAdd(&sh[bv & 1023u], 1u);
        }
    }
    __syncthreads();
    unsigned int* dst = (LEVEL == 1) ? g_hist1 : g_hist2;
    for (int t = tid; t < NB; t += blockDim.x)
        if (sh[t]) atomicAdd(&dst[t], sh[t]);
}

// ---------------- count <= v1, min of elements > v1 ----------------
__global__ void k_cntmin() {
    unsigned v1 = g_prefix;
    unsigned long long cnt = 0ULL;
    unsigned mn = 0xFFFFFFFFu;
    size_t stride = (size_t)gridDim.x * blockDim.x;
    for (size_t idx = (size_t)blockIdx.x * blockDim.x + threadIdx.x; idx < NN; idx += stride) {
        unsigned bv = __float_as_uint(g_M[idx]);
        if (bv <= v1) cnt++;
        else mn = min(mn, bv);
    }
    #pragma unroll
    for (int o = 16; o; o >>= 1) {
        cnt += __shfl_xor_sync(0xFFFFFFFFu, cnt, o);
        mn = min(mn, __shfl_xor_sync(0xFFFFFFFFu, mn, o));
    }
    if ((threadIdx.x & 31) == 0) {
        atomicAdd(&g_cntLE, cnt);
        atomicMin(&g_minGT, mn);
    }
}

// ---------------- median finalize ----------------
__global__ void k_med() {
    float v1 = __uint_as_float(g_prefix);
    float v2 = (g_cntLE >= (unsigned long long)(K1 + 1)) ? v1 : __uint_as_float(g_minGT);
    float med = 0.5f * (v1 + v2);
    if (med > 0.0f) {
        g_invMedReg = 10.0f / med;   // SREG = 0.1
        g_lossScale = 1.0f / med;
    } else {
        g_invMedReg = 10.0f;
        g_lossScale = 1.0f;
    }
}

// ---------------- K' = e^10 * exp(-M * invMedReg)  (fp16) ----------------
__global__ void k_gibbs() {
    float inv = g_invMedReg;
    size_t stride = (size_t)gridDim.x * blockDim.x;
    const float4* Mi = (const float4*)g_M;
    uint4* Ko = (uint4*)g_Kh;
    for (size_t q = (size_t)blockIdx.x * blockDim.x + threadIdx.x; q < NN / 8; q += stride) {
        float4 m0 = Mi[2 * q];
        float4 m1 = Mi[2 * q + 1];
        __half2 h0 = __floats2half2_rn(__expf(10.0f - m0.x * inv), __expf(10.0f - m0.y * inv));
        __half2 h1 = __floats2half2_rn(__expf(10.0f - m0.z * inv), __expf(10.0f - m0.w * inv));
        __half2 h2 = __floats2half2_rn(__expf(10.0f - m1.x * inv), __expf(10.0f - m1.y * inv));
        __half2 h3 = __floats2half2_rn(__expf(10.0f - m1.z * inv), __expf(10.0f - m1.w * inv));
        uint4 o;
        o.x = *(unsigned int*)&h0;
        o.y = *(unsigned int*)&h1;
        o.z = *(unsigned int*)&h2;
        o.w = *(unsigned int*)&h3;
        Ko[q] = o;
    }
}

// -------- tmp_j += sum_i K'_ij u_i  (K'^T u, column-tiled) --------
// grid (4, 64): bx = 256-uint4 column strip, by = 128-row tile. 256 blocks.
__global__ void k_colsum() {
    __shared__ float us[128];
    int tid = threadIdx.x;
    int j8 = blockIdx.x * 256 + tid;            // uint4 column index, 0..1023
    int r0 = blockIdx.y * 128;
    if (tid < 128) us[tid] = g_u[r0 + tid];
    __syncthreads();
    const uint4* Kb = (const uint4*)(g_Kh + (size_t)r0 * NPTS) + j8;
    float a0 = 0.f, a1 = 0.f, a2 = 0.f, a3 = 0.f, a4 = 0.f, a5 = 0.f, a6 = 0.f, a7 = 0.f;
    #pragma unroll 8
    for (int r = 0; r < 128; r++) {
        float uu = us[r];
        uint4 kv = Kb[(size_t)r * (NPTS / 8)];
        float2 f0 = __half22float2(*(__half2*)&kv.x);
        float2 f1 = __half22float2(*(__half2*)&kv.y);
        float2 f2 = __half22float2(*(__half2*)&kv.z);
        float2 f3 = __half22float2(*(__half2*)&kv.w);
        a0 += f0.x * uu; a1 += f0.y * uu;
        a2 += f1.x * uu; a3 += f1.y * uu;
        a4 += f2.x * uu; a5 += f2.y * uu;
        a6 += f3.x * uu; a7 += f3.y * uu;
    }
    int j = j8 * 8;
    atomicAdd(&g_tmp[j + 0], a0); atomicAdd(&g_tmp[j + 1], a1);
    atomicAdd(&g_tmp[j + 2], a2); atomicAdd(&g_tmp[j + 3], a3);
    atomicAdd(&g_tmp[j + 4], a4); atomicAdd(&g_tmp[j + 5], a5);
    atomicAdd(&g_tmp[j + 6], a6); atomicAdd(&g_tmp[j + 7], a7);
}

// ---------------- v' = nu / tmp ; tmp = 0 ----------------
__global__ void k_vupd() {
    int j = blockIdx.x * blockDim.x + threadIdx.x;
    if (j < NPTS) {
        g_v[j] = (1.0f / NPTS) / g_tmp[j];
        g_tmp[j] = 0.0f;
    }
}

// ---------------- u_i = mu / sum_j K'_ij v'_j  (warp per row) ----------------
__global__ void k_rowdot() {
    int warp = threadIdx.x >> 5, lane = threadIdx.x & 31;
    int row = blockIdx.x * 8 + warp;
    const uint4* Kr = (const uint4*)(g_Kh + (size_t)row * NPTS);
    const float4* V = (const float4*)g_v;
    float s0 = 0.f, s1 = 0.f, s2 = 0.f, s3 = 0.f;
    #pragma unroll 8
    for (int c = lane; c < NPTS / 8; c += 32) {
        uint4 kv = Kr[c];
        float4 va = V[2 * c], vb = V[2 * c + 1];
        float2 f0 = __half22float2(*(__half2*)&kv.x);
        float2 f1 = __half22float2(*(__half2*)&kv.y);
        float2 f2 = __half22float2(*(__half2*)&kv.z);
        float2 f3 = __half22float2(*(__half2*)&kv.w);
        s0 += f0.x * va.x + f0.y * va.y;
        s1 += f1.x * va.z + f1.y * va.w;
        s2 += f2.x * vb.x + f2.y * vb.y;
        s3 += f3.x * vb.z + f3.y * vb.w;
    }
    float s = (s0 + s1) + (s2 + s3);
    #pragma unroll
    for (int o = 16; o; o >>= 1) s += __shfl_xor_sync(0xFFFFFFFFu, s, o);
    if (lane == 0) g_u[row] = (1.0f / NPTS) / s;
}

// ---------------- loss = sum u_i K'_ij v'_j M_ij ----------------
__global__ void k_loss() {
    double acc = 0.0;
    size_t stride = (size_t)gridDim.x * blockDim.x;
    const uint4* Kp = (const uint4*)g_Kh;
    const float4* Mp = (const float4*)g_M;
    const float4* Vp = (const float4*)g_v;
    for (size_t q = (size_t)blockIdx.x * blockDim.x + threadIdx.x; q < NN / 8; q += stride) {
        size_t i = q >> 10;          // q*8 / 8192
        int j8 = (int)(q & 1023);
        uint4 kq = Kp[q];
        float4 m0 = Mp[2 * q], m1 = Mp[2 * q + 1];
        float4 va = Vp[2 * j8], vb = Vp[2 * j8 + 1];
        float2 f0 = __half22float2(*(__half2*)&kq.x);
        float2 f1 = __half22float2(*(__half2*)&kq.y);
        float2 f2 = __half22float2(*(__half2*)&kq.z);
        float2 f3 = __half22float2(*(__half2*)&kq.w);
        float ui = g_u[i];
        float t = f0.x * va.x * m0.x + f0.y * va.y * m0.y
                + f1.x * va.z * m0.z + f1.y * va.w * m0.w
                + f2.x * vb.x * m1.x + f2.y * vb.y * m1.y
                + f3.x * vb.z * m1.z + f3.y * vb.w * m1.w;
        acc += (double)ui * (double)t;
    }
    #pragma unroll
    for (int o = 16; o; o >>= 1) acc += __shfl_xor_sync(0xFFFFFFFFu, acc, o);
    __shared__ double sh[8];
    int warp = threadIdx.x >> 5, lane = threadIdx.x & 31;
    if (lane == 0) sh[warp] = acc;
    __syncthreads();
    if (threadIdx.x == 0) {
        double s = 0.0;
        #pragma unroll
        for (int w = 0; w < 8; w++) s += sh[w];
        atomicAdd(&g_loss, s);
    }
}

__global__ void k_out(float* out) {
    out[0] = (float)(g_loss * (double)g_lossScale);
}

extern "C" void kernel_launch(void* const* d_in, const int* in_sizes, int n_in,
                              void* d_out, int out_size) {
    const float* X = (const float*)d_in[0];
    const float* Y = (const float*)d_in[1];

    k_init<<<32, 256>>>();
    k_norms<<<2048, 256>>>(X, Y);
    k_gemm<<<dim3(128, 128), dim3(16, 16)>>>(X, Y);
    k_scan<0><<<1, 256>>>();
    k_hist<1><<<2048, 256>>>();
    k_scan<1><<<1, 256>>>();
    k_hist<2><<<2048, 256>>>();
    k_scan<2><<<1, 256>>>();
    k_cntmin<<<2048, 256>>>();
    k_med<<<1, 1>>>();
    k_gibbs<<<2048, 256>>>();

    for (int it = 0; it < NITER; it++) {
        k_colsum<<<dim3(4, 64), 256>>>();
        k_vupd<<<32, 256>>>();
        k_rowdot<<<1024, 256>>>();
    }

    k_loss<<<1024, 256>>>();
    k_out<<<1, 1>>>((float*)d_out);
}

// round 8
// speedup vs baseline: 1.5242x; 1.0294x over previous
#include <cuda_runtime.h>
#include <cuda_fp16.h>
#include <math.h>

#define NPTS 8192
#define DDIM 64
#define NN ((size_t)NPTS * (size_t)NPTS)
#define NITER 50
#define K1 33554432LL   /* 1-based rank of lower middle element (n*n/2) */

#define PBLOCKS 128
#define PTHREADS 1024

// ---- scratch (no cudaMalloc allowed) ----
__device__ float  g_M[67108864];    // 256 MB cost matrix (unnormalized)
__device__ __half g_Kh[67108864];   // 128 MB scaled Gibbs kernel  K' = e^10 * K
__device__ float g_u[NPTS], g_v[NPTS], g_tmp[NPTS];
__device__ float g_x2[NPTS], g_y2[NPTS];
__device__ unsigned int g_hist0[2048], g_hist1[2048], g_hist2[1024];
__device__ unsigned int g_prefix;
__device__ long long g_k;
__device__ unsigned long long g_cntLE;
__device__ unsigned int g_minGT;
__device__ volatile unsigned int g_barCount;
__device__ volatile unsigned int g_barGen;
__device__ float g_invMedReg;       // 10/med
__device__ float g_lossScale;       // 1/med
__device__ double g_loss;

// ---------------- init ----------------
__global__ void k_init() {
    int idx = blockIdx.x * blockDim.x + threadIdx.x;
    if (idx < NPTS) { g_u[idx] = 1.0f / NPTS; g_tmp[idx] = 0.0f; }
    if (idx < 2048) { g_hist0[idx] = 0u; g_hist1[idx] = 0u; }
    if (idx < 1024) g_hist2[idx] = 0u;
    if (idx == 0) {
        g_loss = 0.0;
        g_prefix = 0u;
        g_k = K1;
        g_cntLE = 0ULL;
        g_minGT = 0xFFFFFFFFu;
        g_barCount = 0u;
        g_barGen = 0u;
    }
}

// ---------------- row norms (warp per row) ----------------
__global__ void k_norms(const float* __restrict__ X, const float* __restrict__ Y) {
    int gw = (blockIdx.x * blockDim.x + threadIdx.x) >> 5;
    int lane = threadIdx.x & 31;
    if (gw >= 2 * NPTS) return;
    const float* src = (gw < NPTS) ? X : Y;
    int row = (gw < NPTS) ? gw : gw - NPTS;
    float2 p = ((const float2*)(src + (size_t)row * DDIM))[lane];
    float s = p.x * p.x + p.y * p.y;
    #pragma unroll
    for (int o = 16; o; o >>= 1) s += __shfl_xor_sync(0xFFFFFFFFu, s, o);
    if (lane == 0) { if (gw < NPTS) g_x2[row] = s; else g_y2[row] = s; }
}

// ---------------- M = sq-cdist GEMM + fused level-0 histogram ----------------
__global__ void k_gemm(const float* __restrict__ X, const float* __restrict__ Y) {
    __shared__ float Xs[64][65];
    __shared__ float Ys[64][65];
    __shared__ unsigned int sh[2048];
    int tx = threadIdx.x, ty = threadIdx.y;
    int tid = ty * 16 + tx;
    int lane = tid & 31;
    int i0 = blockIdx.y * 64, j0 = blockIdx.x * 64;

    for (int t = tid; t < 2048; t += 256) sh[t] = 0u;
    for (int t = tid; t < 4096; t += 256) {
        int r = t >> 6, c = t & 63;
        Xs[r][c] = X[(size_t)(i0 + r) * DDIM + c];
        Ys[r][c] = Y[(size_t)(j0 + r) * DDIM + c];
    }
    __syncthreads();

    float acc[4][4] = {};
    #pragma unroll 16
    for (int k = 0; k < 64; k++) {
        float a[4], b[4];
        #pragma unroll
        for (int r = 0; r < 4; r++) a[r] = Xs[ty * 4 + r][k];
        #pragma unroll
        for (int c = 0; c < 4; c++) b[c] = Ys[tx * 4 + c][k];
        #pragma unroll
        for (int r = 0; r < 4; r++)
            #pragma unroll
            for (int c = 0; c < 4; c++) acc[r][c] += a[r] * b[c];
    }

    #pragma unroll
    for (int r = 0; r < 4; r++) {
        int i = i0 + ty * 4 + r;
        float xi = g_x2[i];
        float4 outv;
        float* o = &outv.x;
        #pragma unroll
        for (int c = 0; c < 4; c++) {
            int j = j0 + tx * 4 + c;
            float m = fmaxf(xi + g_y2[j] - 2.0f * acc[r][c], 0.0f);
            o[c] = m;
            unsigned bin = __float_as_uint(m) >> 21;
            unsigned mask = __match_any_sync(0xFFFFFFFFu, bin);
            if (lane == (__ffs(mask) - 1)) atomicAdd(&sh[bin], (unsigned)__popc(mask));
        }
        *(float4*)&g_M[(size_t)i * NPTS + j0 + tx * 4] = outv;
    }
    __syncthreads();
    for (int t = tid; t < 2048; t += 256)
        if (sh[t]) atomicAdd(&g_hist0[t], sh[t]);
}

// ---------------- radix-select scan (block-cooperative, compile-time level) ----------------
template <int LEVEL>
__global__ void k_scan() {
    constexpr int BITS = (LEVEL < 2) ? 11 : 10;
    constexpr int PER = (1 << BITS) >> 8;   // 8 or 4
    __shared__ unsigned int sums[256];
    __shared__ int sh_b;
    __shared__ long long sh_k;
    int t = threadIdx.x;
    const unsigned int* hist = (LEVEL == 0) ? g_hist0 : (LEVEL == 1) ? g_hist1 : g_hist2;
    unsigned int vals[PER];
    unsigned int local = 0;
    #pragma unroll
    for (int i = 0; i < PER; i++) { vals[i] = hist[t * PER + i]; local += vals[i]; }
    sums[t] = local;
    __syncthreads();
    if (t == 0) {
        long long k = g_k, c = 0;
        int b = 0;
        for (; b < 255; b++) {
            long long h = (long long)sums[b];
            if (c + h >= k) break;
            c += h;
        }
        sh_b = b;
        sh_k = k - c;
    }
    __syncthreads();
    if (t == sh_b) {
        long long k2 = sh_k, c = 0;
        int sel = PER - 1;
        #pragma unroll
        for (int i = 0; i < PER - 1; i++) {
            long long h = (long long)vals[i];
            if (sel == PER - 1) {
                if (c + h >= k2) sel = i;
                else c += h;
            }
        }
        g_k = k2 - c;
        g_prefix = (g_prefix << BITS) | (unsigned)(t * PER + sel);
    }
}

// ---------------- filtered histogram passes (levels 1, 2) ----------------
template <int LEVEL>
__global__ void k_hist() {
    constexpr int NB = (LEVEL == 1) ? 2048 : 1024;
    __shared__ unsigned int sh[NB];
    int tid = threadIdx.x;
    for (int t = tid; t < NB; t += blockDim.x) sh[t] = 0u;
    __syncthreads();
    unsigned pref = g_prefix;
    size_t stride = (size_t)gridDim.x * blockDim.x;
    for (size_t idx = (size_t)blockIdx.x * blockDim.x + tid; idx < NN; idx += stride) {
        unsigned bv = __float_as_uint(g_M[idx]);
        if (LEVEL == 1) {
            if ((bv >> 21) == pref) atomicAdd(&sh[(bv >> 10) & 2047u], 1u);
        } else {
            if ((bv >> 10) == pref) atomicAdd(&sh[bv & 1023u], 1u);
        }
    }
    __syncthreads();
    unsigned int* dst = (LEVEL == 1) ? g_hist1 : g_hist2;
    for (int t = tid; t < NB; t += blockDim.x)
        if (sh[t]) atomicAdd(&dst[t], sh[t]);
}

// ---------------- count <= v1, min of elements > v1 ----------------
__global__ void k_cntmin() {
    unsigned v1 = g_prefix;
    unsigned long long cnt = 0ULL;
    unsigned mn = 0xFFFFFFFFu;
    size_t stride = (size_t)gridDim.x * blockDim.x;
    for (size_t idx = (size_t)blockIdx.x * blockDim.x + threadIdx.x; idx < NN; idx += stride) {
        unsigned bv = __float_as_uint(g_M[idx]);
        if (bv <= v1) cnt++;
        else mn = min(mn, bv);
    }
    #pragma unroll
    for (int o = 16; o; o >>= 1) {
        cnt += __shfl_xor_sync(0xFFFFFFFFu, cnt, o);
        mn = min(mn, __shfl_xor_sync(0xFFFFFFFFu, mn, o));
    }
    if ((threadIdx.x & 31) == 0) {
        atomicAdd(&g_cntLE, cnt);
        atomicMin(&g_minGT, mn);
    }
}

// ---------------- median finalize ----------------
__global__ void k_med() {
    float v1 = __uint_as_float(g_prefix);
    float v2 = (g_cntLE >= (unsigned long long)(K1 + 1)) ? v1 : __uint_as_float(g_minGT);
    float med = 0.5f * (v1 + v2);
    if (med > 0.0f) {
        g_invMedReg = 10.0f / med;   // SREG = 0.1
        g_lossScale = 1.0f / med;
    } else {
        g_invMedReg = 10.0f;
        g_lossScale = 1.0f;
    }
}

// ---------------- K' = e^10 * exp(-M * invMedReg)  (fp16) ----------------
__global__ void k_gibbs() {
    float inv = g_invMedReg;
    size_t stride = (size_t)gridDim.x * blockDim.x;
    const float4* Mi = (const float4*)g_M;
    uint4* Ko = (uint4*)g_Kh;
    for (size_t q = (size_t)blockIdx.x * blockDim.x + threadIdx.x; q < NN / 8; q += stride) {
        float4 m0 = Mi[2 * q];
        float4 m1 = Mi[2 * q + 1];
        __half2 h0 = __floats2half2_rn(__expf(10.0f - m0.x * inv), __expf(10.0f - m0.y * inv));
        __half2 h1 = __floats2half2_rn(__expf(10.0f - m0.z * inv), __expf(10.0f - m0.w * inv));
        __half2 h2 = __floats2half2_rn(__expf(10.0f - m1.x * inv), __expf(10.0f - m1.y * inv));
        __half2 h3 = __floats2half2_rn(__expf(10.0f - m1.z * inv), __expf(10.0f - m1.w * inv));
        uint4 o;
        o.x = *(unsigned int*)&h0;
        o.y = *(unsigned int*)&h1;
        o.z = *(unsigned int*)&h2;
        o.w = *(unsigned int*)&h3;
        Ko[q] = o;
    }
}

// ---------------- persistent Sinkhorn loop ----------------
// 128 blocks x 1024 threads; all blocks co-resident (grid <= #SMs, 1 block/SM),
// so a spin grid-barrier is safe. Sense-reversing generation barrier.
__device__ __forceinline__ void grid_sync() {
    __syncthreads();
    if (threadIdx.x == 0) {
        __threadfence();
        unsigned gen = g_barGen;
        if (atomicAdd((unsigned int*)&g_barCount, 1u) == PBLOCKS - 1) {
            g_barCount = 0u;
            __threadfence();
            g_barGen = gen + 1u;
        } else {
            while (g_barGen == gen) { __nanosleep(32); }
        }
        __threadfence();
    }
    __syncthreads();
}

__global__ void __launch_bounds__(PTHREADS, 1) k_sink() {
    int tid = threadIdx.x;
    int bid = blockIdx.x;
    int lane = tid & 31;
    int warp = tid >> 5;
    __shared__ float us[64];

    for (int it = 0; it < NITER; it++) {
        // ---- Phase A: tmp_j = sum_i K'_ij u_i  (block owns 64 rows, thread owns uint4-col tid)
        int r0 = bid * 64;
        if (tid < 64) us[tid] = g_u[r0 + tid];
        __syncthreads();
        {
            const uint4* Kb = (const uint4*)(g_Kh + (size_t)r0 * NPTS) + tid;
            float a0 = 0.f, a1 = 0.f, a2 = 0.f, a3 = 0.f, a4 = 0.f, a5 = 0.f, a6 = 0.f, a7 = 0.f;
            #pragma unroll 8
            for (int r = 0; r < 64; r++) {
                float uu = us[r];
                uint4 kv = Kb[(size_t)r * (NPTS / 8)];
                float2 f0 = __half22float2(*(__half2*)&kv.x);
                float2 f1 = __half22float2(*(__half2*)&kv.y);
                float2 f2 = __half22float2(*(__half2*)&kv.z);
                float2 f3 = __half22float2(*(__half2*)&kv.w);
                a0 += f0.x * uu; a1 += f0.y * uu;
                a2 += f1.x * uu; a3 += f1.y * uu;
                a4 += f2.x * uu; a5 += f2.y * uu;
                a6 += f3.x * uu; a7 += f3.y * uu;
            }
            int j = tid * 8;
            atomicAdd(&g_tmp[j + 0], a0); atomicAdd(&g_tmp[j + 1], a1);
            atomicAdd(&g_tmp[j + 2], a2); atomicAdd(&g_tmp[j + 3], a3);
            atomicAdd(&g_tmp[j + 4], a4); atomicAdd(&g_tmp[j + 5], a5);
            atomicAdd(&g_tmp[j + 6], a6); atomicAdd(&g_tmp[j + 7], a7);
        }
        grid_sync();

        // ---- Phase B: v = nu / tmp ; tmp = 0   (first 8192 global threads)
        {
            int g = bid * PTHREADS + tid;
            if (g < NPTS) {
                g_v[g] = (1.0f / NPTS) / g_tmp[g];
                g_tmp[g] = 0.0f;
            }
        }
        grid_sync();

        // ---- Phase C: u_i = mu / sum_j K'_ij v_j  (4096 warps x exactly 2 rows)
        {
            int gw = bid * 32 + warp;     // 0..4095
            const float4* V = (const float4*)g_v;
            #pragma unroll
            for (int rr = 0; rr < 2; rr++) {
                int row = gw * 2 + rr;
                const uint4* Kr = (const uint4*)(g_Kh + (size_t)row * NPTS);
                float s0 = 0.f, s1 = 0.f, s2 = 0.f, s3 = 0.f;
                #pragma unroll 8
                for (int c = lane; c < NPTS / 8; c += 32) {
                    uint4 kv = Kr[c];
                    float4 va = V[2 * c], vb = V[2 * c + 1];
                    float2 f0 = __half22float2(*(__half2*)&kv.x);
                    float2 f1 = __half22float2(*(__half2*)&kv.y);
                    float2 f2 = __half22float2(*(__half2*)&kv.z);
                    float2 f3 = __half22float2(*(__half2*)&kv.w);
                    s0 += f0.x * va.x + f0.y * va.y;
                    s1 += f1.x * va.z + f1.y * va.w;
                    s2 += f2.x * vb.x + f2.y * vb.y;
                    s3 += f3.x * vb.z + f3.y * vb.w;
                }
                float s = (s0 + s1) + (s2 + s3);
                #pragma unroll
                for (int o = 16; o; o >>= 1) s += __shfl_xor_sync(0xFFFFFFFFu, s, o);
                if (lane == 0) g_u[row] = (1.0f / NPTS) / s;
            }
        }
        grid_sync();
    }
}

// ---------------- loss = sum u_i K'_ij v'_j M_ij ----------------
__global__ void k_loss() {
    double acc = 0.0;
    size_t stride = (size_t)gridDim.x * blockDim.x;
    const uint4* Kp = (const uint4*)g_Kh;
    const float4* Mp = (const float4*)g_M;
    const float4* Vp = (const float4*)g_v;
    for (size_t q = (size_t)blockIdx.x * blockDim.x + threadIdx.x; q < NN / 8; q += stride) {
        size_t i = q >> 10;          // q*8 / 8192
        int j8 = (int)(q & 1023);
        uint4 kq = Kp[q];
        float4 m0 = Mp[2 * q], m1 = Mp[2 * q + 1];
        float4 va = Vp[2 * j8], vb = Vp[2 * j8 + 1];
        float2 f0 = __half22float2(*(__half2*)&kq.x);
        float2 f1 = __half22float2(*(__half2*)&kq.y);
        float2 f2 = __half22float2(*(__half2*)&kq.z);
        float2 f3 = __half22float2(*(__half2*)&kq.w);
        float ui = g_u[i];
        float t = f0.x * va.x * m0.x + f0.y * va.y * m0.y
                + f1.x * va.z * m0.z + f1.y * va.w * m0.w
                + f2.x * vb.x * m1.x + f2.y * vb.y * m1.y
                + f3.x * vb.z * m1.z + f3.y * vb.w * m1.w;
        acc += (double)ui * (double)t;
    }
    #pragma unroll
    for (int o = 16; o; o >>= 1) acc += __shfl_xor_sync(0xFFFFFFFFu, acc, o);
    __shared__ double sh[8];
    int warp = threadIdx.x >> 5, lane = threadIdx.x & 31;
    if (lane == 0) sh[warp] = acc;
    __syncthreads();
    if (threadIdx.x == 0) {
        double s = 0.0;
        #pragma unroll
        for (int w = 0; w < 8; w++) s += sh[w];
        atomicAdd(&g_loss, s);
    }
}

__global__ void k_out(float* out) {
    out[0] = (float)(g_loss * (double)g_lossScale);
}

extern "C" void kernel_launch(void* const* d_in, const int* in_sizes, int n_in,
                              void* d_out, int out_size) {
    const float* X = (const float*)d_in[0];
    const float* Y = (const float*)d_in[1];

    k_init<<<32, 256>>>();
    k_norms<<<2048, 256>>>(X, Y);
    k_gemm<<<dim3(128, 128), dim3(16, 16)>>>(X, Y);
    k_scan<0><<<1, 256>>>();
    k_hist<1><<<2048, 256>>>();
    k_scan<1><<<1, 256>>>();
    k_hist<2><<<2048, 256>>>();
    k_scan<2><<<1, 256>>>();
    k_cntmin<<<2048, 256>>>();
    k_med<<<1, 1>>>();
    k_gibbs<<<2048, 256>>>();

    k_sink<<<PBLOCKS, PTHREADS>>>();

    k_loss<<<1024, 256>>>();
    k_out<<<1, 1>>>((float*)d_out);
}